// round 16
// baseline (speedup 1.0000x reference)
#include <cuda_runtime.h>
#include <cuda_bf16.h>
#include <cmath>
#include <cstdint>

#define TOKENS 8192
#define SEQ 2048
#define DM 512
#define DFF 2048
#define NLAYER 12
#define NVOCAB 400
#define NP 16
#define PLEN 128

typedef __nv_bfloat16 bf16;

// ---------------- scratch (device globals) ----------------
__device__ __align__(16) float g_h[TOKENS * DM];
__device__ __align__(16) float g_qkv[TOKENS * 3 * DM];
__device__ __align__(16) bf16  g_h_hi[TOKENS * DM];
__device__ __align__(16) bf16  g_h_lo[TOKENS * DM];
__device__ __align__(16) bf16  g_attn_hi[TOKENS * DM];
__device__ __align__(16) bf16  g_attn_lo[TOKENS * DM];
__device__ __align__(16) bf16  g_ff_hi[TOKENS * DFF];
__device__ __align__(16) bf16  g_ff_lo[TOKENS * DFF];
// split weights [K][N] layout: qkv | wo | w1 | w2
#define OFF_QKV 0
#define OFF_WO  (NLAYER * 3 * DM * DM)
#define OFF_W1  (OFF_WO + NLAYER * DM * DM)
#define OFF_W2  (OFF_W1 + NLAYER * DM * DFF)
#define W_TOTAL (OFF_W2 + NLAYER * DFF * DM)
__device__ __align__(16) bf16 g_w_hi[W_TOTAL];
__device__ __align__(16) bf16 g_w_lo[W_TOTAL];
// padded out-projection weights/bias
__device__ __align__(16) bf16 g_wout_hi[DM * DM];
__device__ __align__(16) bf16 g_wout_lo[DM * DM];
__device__ __align__(16) float g_bout[DM];
// attention partials
__device__ float g_state[32 * NP * 64 * 64];
__device__ float g_z[32 * NP * 64];

static __device__ __forceinline__ unsigned sptr(const void* p) {
    return (unsigned)__cvta_generic_to_shared(p);
}

static __device__ __forceinline__ void split2(float x, float y,
                                              unsigned& hi, unsigned& lo)
{
    __nv_bfloat162 h = __floats2bfloat162_rn(x, y);
    float rx = x - __bfloat162float(h.x);
    float ry = y - __bfloat162float(h.y);
    __nv_bfloat162 l = __floats2bfloat162_rn(rx, ry);
    hi = *reinterpret_cast<unsigned*>(&h);
    lo = *reinterpret_cast<unsigned*>(&l);
}

// ---------------- weight split ----------------
__global__ void __launch_bounds__(256) split_kernel(const float* __restrict__ src,
                                                    bf16* __restrict__ hi,
                                                    bf16* __restrict__ lo, int n4)
{
    int i = blockIdx.x * 256 + threadIdx.x;
    if (i >= n4) return;
    float4 f = ((const float4*)src)[i];
    unsigned h0, l0, h1, l1;
    split2(f.x, f.y, h0, l0);
    split2(f.z, f.w, h1, l1);
    ((uint2*)hi)[i] = make_uint2(h0, h1);
    ((uint2*)lo)[i] = make_uint2(l0, l1);
}

// ---------------- out-proj pad+split: Wout[512][400] -> [512][512] hi/lo ----------------
__global__ void __launch_bounds__(128) wout_split_kernel(const float* __restrict__ W,
                                                         bf16* __restrict__ hi,
                                                         bf16* __restrict__ lo)
{
    int k = blockIdx.x;
    int n = threadIdx.x * 4;
    float v0 = (n + 0 < NVOCAB) ? W[(size_t)k * NVOCAB + n + 0] : 0.0f;
    float v1 = (n + 1 < NVOCAB) ? W[(size_t)k * NVOCAB + n + 1] : 0.0f;
    float v2 = (n + 2 < NVOCAB) ? W[(size_t)k * NVOCAB + n + 2] : 0.0f;
    float v3 = (n + 3 < NVOCAB) ? W[(size_t)k * NVOCAB + n + 3] : 0.0f;
    unsigned h0, l0, h1, l1;
    split2(v0, v1, h0, l0);
    split2(v2, v3, h1, l1);
    ((uint2*)(hi + (size_t)k * DM + n))[0] = make_uint2(h0, h1);
    ((uint2*)(lo + (size_t)k * DM + n))[0] = make_uint2(l0, l1);
}

__global__ void bpad_kernel(const float* __restrict__ b, float* __restrict__ bp)
{
    int i = threadIdx.x;
    bp[i] = (i < NVOCAB) ? b[i] : 0.0f;
}

// ---------------- embedding + PE (hi/lo only) ----------------
__global__ void embed_kernel(const int* __restrict__ x, const float* __restrict__ emb,
                             bf16* __restrict__ hhi, bf16* __restrict__ hlo)
{
    int t = blockIdx.x;
    int s = t & (SEQ - 1);
    int tok = x[t];
    const float C1 = -9.210340371976184f / 512.0f;
    for (int d = threadIdx.x; d < DM; d += blockDim.x) {
        int p = d >> 1;
        float div = expf((float)(2 * p) * C1);
        float ang = (float)s * div;
        float pe = (d & 1) ? cosf(ang) : sinf(ang);
        float v = emb[(size_t)tok * DM + d] * 22.62741699796952f + pe;
        bf16 hv = __float2bfloat16(v);
        hhi[(size_t)t * DM + d] = hv;
        hlo[(size_t)t * DM + d] = __float2bfloat16(v - __bfloat162float(hv));
    }
}

// ---------------- LayerNorm: fp32 in -> hi/lo out (+ optional fp32 out) ----------------
__global__ void __launch_bounds__(128) ln_kernel(const float* __restrict__ in,
                                                 const float* __restrict__ g,
                                                 const float* __restrict__ b,
                                                 float* __restrict__ out,
                                                 bf16* __restrict__ ohi,
                                                 bf16* __restrict__ olo)
{
    __shared__ float sh[8];
    int row = blockIdx.x;
    int t = threadIdx.x;
    float4 x = ((const float4*)(in + (size_t)row * DM))[t];

    float s = x.x + x.y + x.z + x.w;
    #pragma unroll
    for (int o = 16; o > 0; o >>= 1) s += __shfl_xor_sync(0xffffffffu, s, o);
    if ((t & 31) == 0) sh[t >> 5] = s;
    __syncthreads();
    float mean = (sh[0] + sh[1] + sh[2] + sh[3]) * (1.0f / DM);

    float dx = x.x - mean, dy = x.y - mean, dz = x.z - mean, dw = x.w - mean;
    float sq = dx * dx + dy * dy + dz * dz + dw * dw;
    #pragma unroll
    for (int o = 16; o > 0; o >>= 1) sq += __shfl_xor_sync(0xffffffffu, sq, o);
    if ((t & 31) == 0) sh[4 + (t >> 5)] = sq;
    __syncthreads();
    float var = (sh[4] + sh[5] + sh[6] + sh[7]) * (1.0f / DM);
    float rs = rsqrtf(var + 1e-5f);

    float4 gg = ((const float4*)g)[t];
    float4 bb = ((const float4*)b)[t];
    float4 o4;
    o4.x = dx * rs * gg.x + bb.x;
    o4.y = dy * rs * gg.y + bb.y;
    o4.z = dz * rs * gg.z + bb.z;
    o4.w = dw * rs * gg.w + bb.w;
    if (out) ((float4*)(out + (size_t)row * DM))[t] = o4;
    unsigned h0, l0, h1, l1;
    split2(o4.x, o4.y, h0, l0);
    split2(o4.z, o4.w, h1, l1);
    ((uint2*)(ohi + (size_t)row * DM))[t] = make_uint2(h0, h1);
    ((uint2*)(olo + (size_t)row * DM))[t] = make_uint2(l0, l1);
}

// ---------------- attention pass 1 (R12-proven scalar form) ----------------
__global__ void __launch_bounds__(64) attn_sums_kernel(const float* __restrict__ qkv,
                                                       float* __restrict__ state,
                                                       float* __restrict__ zbuf)
{
    int bh = blockIdx.x, p = blockIdx.y;
    int b = bh >> 3, hh = bh & 7;
    int e = threadIdx.x;

    __shared__ float ks[32][64];
    __shared__ float vs[32][64];

    float S[64];
    #pragma unroll
    for (int d = 0; d < 64; d++) S[d] = 0.0f;
    float zc = 0.0f;

    const float* base = qkv + (size_t)b * SEQ * (3 * DM) + hh * 64;

    for (int c0 = p * PLEN; c0 < p * PLEN + PLEN; c0 += 32) {
        #pragma unroll 4
        for (int j = 0; j < 32; j++) {
            const float* r = base + (size_t)(c0 + j) * (3 * DM);
            float kv = r[DM + e], vv = r[2 * DM + e];
            ks[j][e] = (kv > 0.0f) ? kv + 1.0f : expf(kv);
            vs[j][e] = vv;
        }
        __syncthreads();
        for (int j = 0; j < 32; j++) {
            float ve = vs[j][e];
            zc += ks[j][e];
            #pragma unroll
            for (int d = 0; d < 64; d++) S[d] = fmaf(ks[j][d], ve, S[d]);
        }
        __syncthreads();
    }

    float* st = state + ((size_t)bh * NP + p) * 4096;
    #pragma unroll 4
    for (int d = 0; d < 64; d++) st[d * 64 + e] = S[d];
    zbuf[((size_t)bh * NP + p) * 64 + e] = zc;
}

// ---------------- attention pass 2: exclusive prefix ----------------
__global__ void __launch_bounds__(256) attn_prefix_kernel(float* __restrict__ state,
                                                          float* __restrict__ zbuf)
{
    int bh = blockIdx.x;
    int e = threadIdx.x & 63;
    int dg = threadIdx.x >> 6;

    float acc[16];
    #pragma unroll
    for (int i = 0; i < 16; i++) acc[i] = 0.0f;
    float zacc = 0.0f;

    for (int p = 0; p < NP; p++) {
        float* st = state + ((size_t)bh * NP + p) * 4096;
        #pragma unroll
        for (int i = 0; i < 16; i++) {
            int d = dg * 16 + i;
            float t = st[d * 64 + e];
            st[d * 64 + e] = acc[i];
            acc[i] += t;
        }
        if (dg == 0) {
            float* z = zbuf + ((size_t)bh * NP + p) * 64;
            float t = z[e];
            z[e] = zacc;
            zacc += t;
        }
    }
}

// ---------------- attention pass 3: scan (R12-proven scalar form) ----------------
__global__ void __launch_bounds__(64) attn_scan_kernel(const float* __restrict__ qkv,
                                                       const float* __restrict__ state,
                                                       const float* __restrict__ zbuf,
                                                       bf16* __restrict__ ohi,
                                                       bf16* __restrict__ olo)
{
    int bh = blockIdx.x, p = blockIdx.y;
    int b = bh >> 3, hh = bh & 7;
    int e = threadIdx.x;

    __shared__ float ks[32][64];
    __shared__ float qs[32][64];
    __shared__ float vs[32][64];
    __shared__ float ps[32][65];
    __shared__ float dens[32];

    float S[64];
    const float* st = state + ((size_t)bh * NP + p) * 4096;
    #pragma unroll 4
    for (int d = 0; d < 64; d++) S[d] = st[d * 64 + e];
    float zc = zbuf[((size_t)bh * NP + p) * 64 + e];

    const float* base = qkv + (size_t)b * SEQ * (3 * DM) + hh * 64;
    size_t obase = (size_t)b * SEQ * DM + hh * 64 + e;

    for (int c0 = p * PLEN; c0 < p * PLEN + PLEN; c0 += 32) {
        #pragma unroll 4
        for (int j = 0; j < 32; j++) {
            const float* r = base + (size_t)(c0 + j) * (3 * DM);
            float qv = r[e], kv = r[DM + e], vv = r[2 * DM + e];
            qs[j][e] = (qv > 0.0f) ? qv + 1.0f : expf(qv);
            ks[j][e] = (kv > 0.0f) ? kv + 1.0f : expf(kv);
            vs[j][e] = vv;
        }
        __syncthreads();

        float z = zc;
        #pragma unroll
        for (int j = 0; j < 32; j++) { z += ks[j][e]; ps[j][e] = qs[j][e] * z; }
        zc = z;
        __syncthreads();

        if (e < 32) {
            float sum = 0.0f;
            #pragma unroll 8
            for (int d = 0; d < 64; d++) sum += ps[e][d];
            dens[e] = sum + 1e-6f;
        }
        __syncthreads();

        for (int j = 0; j < 32; j++) {
            float ve = vs[j][e];
            float n0 = 0.f, n1 = 0.f, n2 = 0.f, n3 = 0.f;
            #pragma unroll
            for (int d = 0; d < 64; d += 4) {
                S[d + 0] = fmaf(ks[j][d + 0], ve, S[d + 0]); n0 = fmaf(qs[j][d + 0], S[d + 0], n0);
                S[d + 1] = fmaf(ks[j][d + 1], ve, S[d + 1]); n1 = fmaf(qs[j][d + 1], S[d + 1], n1);
                S[d + 2] = fmaf(ks[j][d + 2], ve, S[d + 2]); n2 = fmaf(qs[j][d + 2], S[d + 2], n2);
                S[d + 3] = fmaf(ks[j][d + 3], ve, S[d + 3]); n3 = fmaf(qs[j][d + 3], S[d + 3], n3);
            }
            float o = ((n0 + n1) + (n2 + n3)) / dens[j];
            bf16 hv = __float2bfloat16(o);
            size_t idx = obase + (size_t)(c0 + j) * DM;
            ohi[idx] = hv;
            olo[idx] = __float2bfloat16(o - __bfloat162float(hv));
        }
        __syncthreads();
    }
}

// ================= bf16x3 tensor GEMM (R12 loop; residual from hi/lo) =================
// C = (Ahi+Alo)[M,K] @ (Bhi+Blo)[K,N] + bias (+ (Rhi+Rlo)) (relu?)
#define ASB 72
#define BSB 264
#define AS_E (128 * ASB)
#define BS_E (32 * BSB)
#define TG_SMEM ((AS_E + BS_E) * 2 * 2)

#define MMA_BF16(d, a, b) \
    asm volatile("mma.sync.aligned.m16n8k16.row.col.f32.bf16.bf16.f32 " \
                 "{%0,%1,%2,%3},{%4,%5,%6,%7},{%8,%9},{%0,%1,%2,%3};" \
                 : "+f"((d)[0]), "+f"((d)[1]), "+f"((d)[2]), "+f"((d)[3]) \
                 : "r"((a)[0]), "r"((a)[1]), "r"((a)[2]), "r"((a)[3]), \
                   "r"((b)[0]), "r"((b)[1]))

template <bool RELU, bool RES, bool WF32, bool WBF>
__global__ void __launch_bounds__(256, 2) tgemm_kernel(
    const bf16* __restrict__ Ahi, const bf16* __restrict__ Alo,
    const bf16* __restrict__ Bhi, const bf16* __restrict__ Blo,
    const float* __restrict__ bias,
    const bf16* __restrict__ Rhi, const bf16* __restrict__ Rlo,
    float* __restrict__ C, bf16* __restrict__ Chi, bf16* __restrict__ Clo,
    int K, int ldb, int nPerChunk, size_t chunkStride, int ldc, int Nmax)
{
    extern __shared__ __align__(16) unsigned char smem_raw[];
    bf16* As = (bf16*)smem_raw;
    bf16* Bs = As + 2 * AS_E;

    int tid = threadIdx.x;
    int m0 = blockIdx.y * 128;
    int n0 = blockIdx.x * 128;
    int chunk = n0 / nPerChunk;
    size_t boff = (size_t)chunk * chunkStride + (n0 % nPerChunk);
    const bf16* Bbh = Bhi + boff;
    const bf16* Bbl = Blo + boff;

    int arow = tid >> 1, acol = (tid & 1) * 16;
    int brow = tid >> 3, bcol = (tid & 7) * 16;
    const bf16* Agh = Ahi + (size_t)(m0 + arow) * K + acol;
    const bf16* Agl = Alo + (size_t)(m0 + arow) * K + acol;

    int warp = tid >> 5, lane = tid & 31;
    int wm = (warp >> 2) * 64, wn = (warp & 3) * 32;
    int g = lane >> 2, ctg = lane & 3;
    int lrow = lane & 15, lcol8 = (lane >> 4) * 8;

    float acc[4][4][4];
    #pragma unroll
    for (int i = 0; i < 4; i++)
        #pragma unroll
        for (int j = 0; j < 4; j++)
            #pragma unroll
            for (int r = 0; r < 4; r++) acc[i][j][r] = 0.0f;

    int nt = K / 32;

    auto issue = [&](int kt, int buf) {
        bf16* as = As + buf * AS_E;
        bf16* bs = Bs + buf * BS_E;
        {
            unsigned d0 = sptr(as + arow * ASB + acol);
            unsigned d1 = sptr(as + arow * ASB + 32 + acol);
            const bf16* s0 = Agh + kt * 32;
            const bf16* s1 = Agl + kt * 32;
            asm volatile("cp.async.cg.shared.global [%0], [%1], 16;" :: "r"(d0), "l"(s0));
            asm volatile("cp.async.cg.shared.global [%0], [%1], 16;" :: "r"(d0 + 16), "l"(s0 + 8));
            asm volatile("cp.async.cg.shared.global [%0], [%1], 16;" :: "r"(d1), "l"(s1));
            asm volatile("cp.async.cg.shared.global [%0], [%1], 16;" :: "r"(d1 + 16), "l"(s1 + 8));
        }
        {
            unsigned d0 = sptr(bs + brow * BSB + bcol);
            unsigned d1 = sptr(bs + brow * BSB + 128 + bcol);
            const bf16* s0 = Bbh + (size_t)(kt * 32 + brow) * ldb + bcol;
            const bf16* s1 = Bbl + (size_t)(kt * 32 + brow) * ldb + bcol;
            asm volatile("cp.async.cg.shared.global [%0], [%1], 16;" :: "r"(d0), "l"(s0));
            asm volatile("cp.async.cg.shared.global [%0], [%1], 16;" :: "r"(d0 + 16), "l"(s0 + 8));
            asm volatile("cp.async.cg.shared.global [%0], [%1], 16;" :: "r"(d1), "l"(s1));
            asm volatile("cp.async.cg.shared.global [%0], [%1], 16;" :: "r"(d1 + 16), "l"(s1 + 8));
        }
        asm volatile("cp.async.commit_group;");
    };

    issue(0, 0);
    issue(1, 1);

    for (int kt = 0; kt < nt; kt++) {
        if (kt + 1 < nt) asm volatile("cp.async.wait_group 1;");
        else             asm volatile("cp.async.wait_group 0;");
        __syncthreads();

        const bf16* as = As + (kt & 1) * AS_E;
        const bf16* bs = Bs + (kt & 1) * BS_E;

        #pragma unroll
        for (int ks = 0; ks < 32; ks += 16) {
            unsigned bh[4][2], bl[4][2];
            #pragma unroll
            for (int nj = 0; nj < 2; nj++) {
                unsigned addr = sptr(bs + (ks + lrow) * BSB + wn + 16 * nj + lcol8);
                unsigned t0, t1, t2, t3;
                asm volatile("ldmatrix.sync.aligned.m8n8.x4.trans.shared.b16 "
                             "{%0,%1,%2,%3}, [%4];"
                             : "=r"(t0), "=r"(t1), "=r"(t2), "=r"(t3) : "r"(addr));
                bh[2 * nj][0] = t0; bh[2 * nj][1] = t1;
                bh[2 * nj + 1][0] = t2; bh[2 * nj + 1][1] = t3;
                asm volatile("ldmatrix.sync.aligned.m8n8.x4.trans.shared.b16 "
                             "{%0,%1,%2,%3}, [%4];"
                             : "=r"(t0), "=r"(t1), "=r"(t2), "=r"(t3)
                             : "r"(addr + 256));   // lo: +128 elems = +256B
                bl[2 * nj][0] = t0; bl[2 * nj][1] = t1;
                bl[2 * nj + 1][0] = t2; bl[2 * nj + 1][1] = t3;
            }
            #pragma unroll
            for (int i = 0; i < 4; i++) {
                unsigned ah[4], al[4];
                unsigned addr = sptr(as + (wm + 16 * i + lrow) * ASB + ks + lcol8);
                asm volatile("ldmatrix.sync.aligned.m8n8.x4.shared.b16 "
                             "{%0,%1,%2,%3}, [%4];"
                             : "=r"(ah[0]), "=r"(ah[1]), "=r"(ah[2]), "=r"(ah[3])
                             : "r"(addr));
                asm volatile("ldmatrix.sync.aligned.m8n8.x4.shared.b16 "
                             "{%0,%1,%2,%3}, [%4];"
                             : "=r"(al[0]), "=r"(al[1]), "=r"(al[2]), "=r"(al[3])
                             : "r"(addr + 64));    // lo: +32 elems = +64B
                #pragma unroll
                for (int j = 0; j < 4; j++) {
                    MMA_BF16(acc[i][j], ah, bh[j]);
                    MMA_BF16(acc[i][j], ah, bl[j]);
                    MMA_BF16(acc[i][j], al, bh[j]);
                }
            }
        }
        __syncthreads();
        if (kt + 2 < nt) issue(kt + 2, kt & 1);
    }

    // ---- epilogue ----
    #pragma unroll
    for (int i = 0; i < 4; i++) {
        int mrow = m0 + wm + 16 * i + g;
        #pragma unroll
        for (int j = 0; j < 4; j++) {
            int n = n0 + wn + 8 * j + 2 * ctg;
            if (n >= Nmax) continue;
            float2 bv = *(const float2*)(bias + n);
            float v0 = acc[i][j][0] + bv.x, v1 = acc[i][j][1] + bv.y;
            float v2 = acc[i][j][2] + bv.x, v3 = acc[i][j][3] + bv.y;
            if (RES) {
                unsigned rh0 = *(const unsigned*)(Rhi + (size_t)mrow * ldc + n);
                unsigned rl0 = *(const unsigned*)(Rlo + (size_t)mrow * ldc + n);
                unsigned rh1 = *(const unsigned*)(Rhi + (size_t)(mrow + 8) * ldc + n);
                unsigned rl1 = *(const unsigned*)(Rlo + (size_t)(mrow + 8) * ldc + n);
                __nv_bfloat162 H0 = *reinterpret_cast<__nv_bfloat162*>(&rh0);
                __nv_bfloat162 L0 = *reinterpret_cast<__nv_bfloat162*>(&rl0);
                __nv_bfloat162 H1 = *reinterpret_cast<__nv_bfloat162*>(&rh1);
                __nv_bfloat162 L1 = *reinterpret_cast<__nv_bfloat162*>(&rl1);
                v0 += __bfloat162float(H0.x) + __bfloat162float(L0.x);
                v1 += __bfloat162float(H0.y) + __bfloat162float(L0.y);
                v2 += __bfloat162float(H1.x) + __bfloat162float(L1.x);
                v3 += __bfloat162float(H1.y) + __bfloat162float(L1.y);
            }
            if (RELU) {
                v0 = fmaxf(v0, 0.0f); v1 = fmaxf(v1, 0.0f);
                v2 = fmaxf(v2, 0.0f); v3 = fmaxf(v3, 0.0f);
            }
            if (WF32) {
                *(float2*)(C + (size_t)mrow * ldc + n) = make_float2(v0, v1);
                *(float2*)(C + (size_t)(mrow + 8) * ldc + n) = make_float2(v2, v3);
            }
            if (WBF) {
                unsigned hp, lp;
                split2(v0, v1, hp, lp);
                *(unsigned*)(Chi + (size_t)mrow * ldc + n) = hp;
                *(unsigned*)(Clo + (size_t)mrow * ldc + n) = lp;
                split2(v2, v3, hp, lp);
                *(unsigned*)(Chi + (size_t)(mrow + 8) * ldc + n) = hp;
                *(unsigned*)(Clo + (size_t)(mrow + 8) * ldc + n) = lp;
            }
        }
    }
}

// ---------------- launch ----------------
extern "C" void kernel_launch(void* const* d_in, const int* in_sizes, int n_in,
                              void* d_out, int out_size)
{
    const int*   x    = (const int*)d_in[0];
    const float* emb  = (const float*)d_in[1];
    const float* Wqkv = (const float*)d_in[2];
    const float* bqkv = (const float*)d_in[3];
    const float* Wo   = (const float*)d_in[4];
    const float* bo   = (const float*)d_in[5];
    const float* ln1g = (const float*)d_in[6];
    const float* ln1b = (const float*)d_in[7];
    const float* W1   = (const float*)d_in[8];
    const float* b1   = (const float*)d_in[9];
    const float* W2   = (const float*)d_in[10];
    const float* b2   = (const float*)d_in[11];
    const float* ln2g = (const float*)d_in[12];
    const float* ln2b = (const float*)d_in[13];
    const float* lnfg = (const float*)d_in[14];
    const float* lnfb = (const float*)d_in[15];
    const float* Wout = (const float*)d_in[16];
    const float* bout = (const float*)d_in[17];
    float* out = (float*)d_out;

    float *h, *qkv, *state, *zbuf, *boutp;
    bf16 *hhi, *hlo, *ahi, *alo, *fhi, *flo, *whi, *wlo, *wohi, *wolo;
    cudaGetSymbolAddress((void**)&h,     g_h);
    cudaGetSymbolAddress((void**)&qkv,   g_qkv);
    cudaGetSymbolAddress((void**)&state, g_state);
    cudaGetSymbolAddress((void**)&zbuf,  g_z);
    cudaGetSymbolAddress((void**)&hhi,   g_h_hi);
    cudaGetSymbolAddress((void**)&hlo,   g_h_lo);
    cudaGetSymbolAddress((void**)&ahi,   g_attn_hi);
    cudaGetSymbolAddress((void**)&alo,   g_attn_lo);
    cudaGetSymbolAddress((void**)&fhi,   g_ff_hi);
    cudaGetSymbolAddress((void**)&flo,   g_ff_lo);
    cudaGetSymbolAddress((void**)&whi,   g_w_hi);
    cudaGetSymbolAddress((void**)&wlo,   g_w_lo);
    cudaGetSymbolAddress((void**)&wohi,  g_wout_hi);
    cudaGetSymbolAddress((void**)&wolo,  g_wout_lo);
    cudaGetSymbolAddress((void**)&boutp, g_bout);

    cudaFuncSetAttribute(tgemm_kernel<false, false, true, false>,
                         cudaFuncAttributeMaxDynamicSharedMemorySize, TG_SMEM);
    cudaFuncSetAttribute(tgemm_kernel<false, true, true, false>,
                         cudaFuncAttributeMaxDynamicSharedMemorySize, TG_SMEM);
    cudaFuncSetAttribute(tgemm_kernel<true, false, false, true>,
                         cudaFuncAttributeMaxDynamicSharedMemorySize, TG_SMEM);

    // weight prep
    split_kernel<<<(OFF_WO) / 4 / 256, 256>>>(Wqkv, whi + OFF_QKV, wlo + OFF_QKV, OFF_WO / 4);
    split_kernel<<<(OFF_W1 - OFF_WO) / 4 / 256, 256>>>(Wo, whi + OFF_WO, wlo + OFF_WO, (OFF_W1 - OFF_WO) / 4);
    split_kernel<<<(OFF_W2 - OFF_W1) / 4 / 256, 256>>>(W1, whi + OFF_W1, wlo + OFF_W1, (OFF_W2 - OFF_W1) / 4);
    split_kernel<<<(W_TOTAL - OFF_W2) / 4 / 256, 256>>>(W2, whi + OFF_W2, wlo + OFF_W2, (W_TOTAL - OFF_W2) / 4);
    wout_split_kernel<<<DM, 128>>>(Wout, wohi, wolo);
    bpad_kernel<<<1, DM>>>(bout, boutp);

    embed_kernel<<<TOKENS, 128>>>(x, emb, hhi, hlo);

    dim3 gQKV(12, TOKENS / 128);
    dim3 gN512(4, TOKENS / 128);
    dim3 gN2048(16, TOKENS / 128);
    dim3 gAttn(32, NP);

    for (int l = 0; l < NLAYER; l++) {
        // qkv = h @ [Wq|Wk|Wv] + b   (fp32 out)
        tgemm_kernel<false, false, true, false><<<gQKV, 256, TG_SMEM>>>(
            hhi, hlo,
            whi + OFF_QKV + (size_t)l * 3 * DM * DM, wlo + OFF_QKV + (size_t)l * 3 * DM * DM,
            bqkv + (size_t)l * 3 * DM, nullptr, nullptr,
            qkv, nullptr, nullptr,
            DM, DM, DM, (size_t)DM * DM, 3 * DM, 3 * DM);

        attn_sums_kernel<<<gAttn, 64>>>(qkv, state, zbuf);
        attn_prefix_kernel<<<32, 256>>>(state, zbuf);
        attn_scan_kernel<<<gAttn, 64>>>(qkv, state, zbuf, ahi, alo);

        // h(fp32) = (hhi+hlo) + attn @ Wo + bo
        tgemm_kernel<false, true, true, false><<<gN512, 256, TG_SMEM>>>(
            ahi, alo,
            whi + OFF_WO + (size_t)l * DM * DM, wlo + OFF_WO + (size_t)l * DM * DM,
            bo + (size_t)l * DM, hhi, hlo,
            h, nullptr, nullptr,
            DM, DM, DM, 0, DM, DM);
        // LN1: hi/lo out only (fp32 not consumed)
        ln_kernel<<<TOKENS, 128>>>(h, ln1g + l * DM, ln1b + l * DM, nullptr, hhi, hlo);

        // ff = relu(h @ W1 + b1)  (bf16 hi/lo out)
        tgemm_kernel<true, false, false, true><<<gN2048, 256, TG_SMEM>>>(
            hhi, hlo,
            whi + OFF_W1 + (size_t)l * DM * DFF, wlo + OFF_W1 + (size_t)l * DM * DFF,
            b1 + (size_t)l * DFF, nullptr, nullptr,
            nullptr, fhi, flo,
            DM, DFF, DFF, 0, DFF, DFF);

        // h(fp32) = (hhi+hlo) + ff @ W2 + b2
        tgemm_kernel<false, true, true, false><<<gN512, 256, TG_SMEM>>>(
            fhi, flo,
            whi + OFF_W2 + (size_t)l * DFF * DM, wlo + OFF_W2 + (size_t)l * DFF * DM,
            b2 + (size_t)l * DM, hhi, hlo,
            h, nullptr, nullptr,
            DFF, DM, DM, 0, DM, DM);
        // LN2: hi/lo out; fp32 out only on last layer (feeds final LN input)
        ln_kernel<<<TOKENS, 128>>>(h, ln2g + l * DM, ln2b + l * DM,
                                   (l == NLAYER - 1) ? h : nullptr, hhi, hlo);
    }

    // final LN: reads fp32 h (written by last LN2), hi/lo out only
    ln_kernel<<<TOKENS, 128>>>(h, lnfg, lnfb, nullptr, hhi, hlo);
    // out = h @ Wout + bout  (tensor path, padded N=512, guarded to 400)
    tgemm_kernel<false, false, true, false><<<gN512, 256, TG_SMEM>>>(
        hhi, hlo, wohi, wolo, boutp, nullptr, nullptr,
        out, nullptr, nullptr,
        DM, DM, DM, 0, NVOCAB, NVOCAB);
}

// round 17
// speedup vs baseline: 1.0494x; 1.0494x over previous
#include <cuda_runtime.h>
#include <cuda_bf16.h>
#include <cmath>
#include <cstdint>

#define TOKENS 8192
#define SEQ 2048
#define DM 512
#define DFF 2048
#define NLAYER 12
#define NVOCAB 400
#define NP 16
#define PLEN 128

typedef __nv_bfloat16 bf16;

// ---------------- scratch (device globals) ----------------
__device__ __align__(16) float g_h[TOKENS * DM];
__device__ __align__(16) float g_qkv[TOKENS * 3 * DM];   // holds phi(q), phi(k), v
__device__ __align__(16) bf16  g_h_hi[TOKENS * DM];
__device__ __align__(16) bf16  g_h_lo[TOKENS * DM];
__device__ __align__(16) bf16  g_attn_hi[TOKENS * DM];
__device__ __align__(16) bf16  g_attn_lo[TOKENS * DM];
__device__ __align__(16) bf16  g_ff_hi[TOKENS * DFF];
__device__ __align__(16) bf16  g_ff_lo[TOKENS * DFF];
// split weights [K][N] layout: qkv | wo | w1 | w2
#define OFF_QKV 0
#define OFF_WO  (NLAYER * 3 * DM * DM)
#define OFF_W1  (OFF_WO + NLAYER * DM * DM)
#define OFF_W2  (OFF_W1 + NLAYER * DM * DFF)
#define W_TOTAL (OFF_W2 + NLAYER * DFF * DM)
__device__ __align__(16) bf16 g_w_hi[W_TOTAL];
__device__ __align__(16) bf16 g_w_lo[W_TOTAL];
// padded out-projection weights/bias
__device__ __align__(16) bf16 g_wout_hi[DM * DM];
__device__ __align__(16) bf16 g_wout_lo[DM * DM];
__device__ __align__(16) float g_bout[DM];
// attention partials
__device__ float g_state[32 * NP * 64 * 64];
__device__ float g_z[32 * NP * 64];

static __device__ __forceinline__ unsigned sptr(const void* p) {
    return (unsigned)__cvta_generic_to_shared(p);
}

static __device__ __forceinline__ void split2(float x, float y,
                                              unsigned& hi, unsigned& lo)
{
    __nv_bfloat162 h = __floats2bfloat162_rn(x, y);
    float rx = x - __bfloat162float(h.x);
    float ry = y - __bfloat162float(h.y);
    __nv_bfloat162 l = __floats2bfloat162_rn(rx, ry);
    hi = *reinterpret_cast<unsigned*>(&h);
    lo = *reinterpret_cast<unsigned*>(&l);
}

// ---------------- weight split ----------------
__global__ void __launch_bounds__(256) split_kernel(const float* __restrict__ src,
                                                    bf16* __restrict__ hi,
                                                    bf16* __restrict__ lo, int n4)
{
    int i = blockIdx.x * 256 + threadIdx.x;
    if (i >= n4) return;
    float4 f = ((const float4*)src)[i];
    unsigned h0, l0, h1, l1;
    split2(f.x, f.y, h0, l0);
    split2(f.z, f.w, h1, l1);
    ((uint2*)hi)[i] = make_uint2(h0, h1);
    ((uint2*)lo)[i] = make_uint2(l0, l1);
}

// ---------------- out-proj pad+split: Wout[512][400] -> [512][512] hi/lo ----------------
__global__ void __launch_bounds__(128) wout_split_kernel(const float* __restrict__ W,
                                                         bf16* __restrict__ hi,
                                                         bf16* __restrict__ lo)
{
    int k = blockIdx.x;
    int n = threadIdx.x * 4;
    float v0 = (n + 0 < NVOCAB) ? W[(size_t)k * NVOCAB + n + 0] : 0.0f;
    float v1 = (n + 1 < NVOCAB) ? W[(size_t)k * NVOCAB + n + 1] : 0.0f;
    float v2 = (n + 2 < NVOCAB) ? W[(size_t)k * NVOCAB + n + 2] : 0.0f;
    float v3 = (n + 3 < NVOCAB) ? W[(size_t)k * NVOCAB + n + 3] : 0.0f;
    unsigned h0, l0, h1, l1;
    split2(v0, v1, h0, l0);
    split2(v2, v3, h1, l1);
    ((uint2*)(hi + (size_t)k * DM + n))[0] = make_uint2(h0, h1);
    ((uint2*)(lo + (size_t)k * DM + n))[0] = make_uint2(l0, l1);
}

__global__ void bpad_kernel(const float* __restrict__ b, float* __restrict__ bp)
{
    int i = threadIdx.x;
    bp[i] = (i < NVOCAB) ? b[i] : 0.0f;
}

// ---------------- embedding + PE (+ hi/lo) ----------------
__global__ void embed_kernel(const int* __restrict__ x, const float* __restrict__ emb,
                             float* __restrict__ h, bf16* __restrict__ hhi,
                             bf16* __restrict__ hlo)
{
    int t = blockIdx.x;
    int s = t & (SEQ - 1);
    int tok = x[t];
    const float C1 = -9.210340371976184f / 512.0f;
    for (int d = threadIdx.x; d < DM; d += blockDim.x) {
        int p = d >> 1;
        float div = expf((float)(2 * p) * C1);
        float ang = (float)s * div;
        float pe = (d & 1) ? cosf(ang) : sinf(ang);
        float v = emb[(size_t)tok * DM + d] * 22.62741699796952f + pe;
        h[(size_t)t * DM + d] = v;
        bf16 hv = __float2bfloat16(v);
        hhi[(size_t)t * DM + d] = hv;
        hlo[(size_t)t * DM + d] = __float2bfloat16(v - __bfloat162float(hv));
    }
}

// ---------------- LayerNorm (+ optional hi/lo) ----------------
__global__ void __launch_bounds__(128) ln_kernel(const float* __restrict__ in,
                                                 const float* __restrict__ g,
                                                 const float* __restrict__ b,
                                                 float* __restrict__ out,
                                                 bf16* __restrict__ ohi,
                                                 bf16* __restrict__ olo)
{
    __shared__ float sh[8];
    int row = blockIdx.x;
    int t = threadIdx.x;
    float4 x = ((const float4*)(in + (size_t)row * DM))[t];

    float s = x.x + x.y + x.z + x.w;
    #pragma unroll
    for (int o = 16; o > 0; o >>= 1) s += __shfl_xor_sync(0xffffffffu, s, o);
    if ((t & 31) == 0) sh[t >> 5] = s;
    __syncthreads();
    float mean = (sh[0] + sh[1] + sh[2] + sh[3]) * (1.0f / DM);

    float dx = x.x - mean, dy = x.y - mean, dz = x.z - mean, dw = x.w - mean;
    float sq = dx * dx + dy * dy + dz * dz + dw * dw;
    #pragma unroll
    for (int o = 16; o > 0; o >>= 1) sq += __shfl_xor_sync(0xffffffffu, sq, o);
    if ((t & 31) == 0) sh[4 + (t >> 5)] = sq;
    __syncthreads();
    float var = (sh[4] + sh[5] + sh[6] + sh[7]) * (1.0f / DM);
    float rs = rsqrtf(var + 1e-5f);

    float4 gg = ((const float4*)g)[t];
    float4 bb = ((const float4*)b)[t];
    float4 o4;
    o4.x = dx * rs * gg.x + bb.x;
    o4.y = dy * rs * gg.y + bb.y;
    o4.z = dz * rs * gg.z + bb.z;
    o4.w = dw * rs * gg.w + bb.w;
    ((float4*)(out + (size_t)row * DM))[t] = o4;
    if (ohi) {
        unsigned h0, l0, h1, l1;
        split2(o4.x, o4.y, h0, l0);
        split2(o4.z, o4.w, h1, l1);
        ((uint2*)(ohi + (size_t)row * DM))[t] = make_uint2(h0, h1);
        ((uint2*)(olo + (size_t)row * DM))[t] = make_uint2(l0, l1);
    }
}

// ---------------- attention pass 1 (phi pre-applied; staging is pure copy) ----------------
__global__ void __launch_bounds__(64) attn_sums_kernel(const float* __restrict__ qkv,
                                                       float* __restrict__ state,
                                                       float* __restrict__ zbuf)
{
    int bh = blockIdx.x, p = blockIdx.y;
    int b = bh >> 3, hh = bh & 7;
    int e = threadIdx.x;

    __shared__ float ks[32][64];
    __shared__ float vs[32][64];

    float S[64];
    #pragma unroll
    for (int d = 0; d < 64; d++) S[d] = 0.0f;
    float zc = 0.0f;

    const float* base = qkv + (size_t)b * SEQ * (3 * DM) + hh * 64;

    for (int c0 = p * PLEN; c0 < p * PLEN + PLEN; c0 += 32) {
        #pragma unroll 4
        for (int j = 0; j < 32; j++) {
            const float* r = base + (size_t)(c0 + j) * (3 * DM);
            ks[j][e] = r[DM + e];       // phi(k) precomputed in GEMM epilogue
            vs[j][e] = r[2 * DM + e];
        }
        __syncthreads();
        for (int j = 0; j < 32; j++) {
            float ve = vs[j][e];
            zc += ks[j][e];
            #pragma unroll
            for (int d = 0; d < 64; d++) S[d] = fmaf(ks[j][d], ve, S[d]);
        }
        __syncthreads();
    }

    float* st = state + ((size_t)bh * NP + p) * 4096;
    #pragma unroll 4
    for (int d = 0; d < 64; d++) st[d * 64 + e] = S[d];
    zbuf[((size_t)bh * NP + p) * 64 + e] = zc;
}

// ---------------- attention pass 2: exclusive prefix ----------------
__global__ void __launch_bounds__(256) attn_prefix_kernel(float* __restrict__ state,
                                                          float* __restrict__ zbuf)
{
    int bh = blockIdx.x;
    int e = threadIdx.x & 63;
    int dg = threadIdx.x >> 6;

    float acc[16];
    #pragma unroll
    for (int i = 0; i < 16; i++) acc[i] = 0.0f;
    float zacc = 0.0f;

    for (int p = 0; p < NP; p++) {
        float* st = state + ((size_t)bh * NP + p) * 4096;
        #pragma unroll
        for (int i = 0; i < 16; i++) {
            int d = dg * 16 + i;
            float t = st[d * 64 + e];
            st[d * 64 + e] = acc[i];
            acc[i] += t;
        }
        if (dg == 0) {
            float* z = zbuf + ((size_t)bh * NP + p) * 64;
            float t = z[e];
            z[e] = zacc;
            zacc += t;
        }
    }
}

// ---------------- attention pass 3: scan (phi pre-applied) ----------------
__global__ void __launch_bounds__(64) attn_scan_kernel(const float* __restrict__ qkv,
                                                       const float* __restrict__ state,
                                                       const float* __restrict__ zbuf,
                                                       bf16* __restrict__ ohi,
                                                       bf16* __restrict__ olo)
{
    int bh = blockIdx.x, p = blockIdx.y;
    int b = bh >> 3, hh = bh & 7;
    int e = threadIdx.x;

    __shared__ float ks[32][64];
    __shared__ float qs[32][64];
    __shared__ float vs[32][64];
    __shared__ float ps[32][65];
    __shared__ float dens[32];

    float S[64];
    const float* st = state + ((size_t)bh * NP + p) * 4096;
    #pragma unroll 4
    for (int d = 0; d < 64; d++) S[d] = st[d * 64 + e];
    float zc = zbuf[((size_t)bh * NP + p) * 64 + e];

    const float* base = qkv + (size_t)b * SEQ * (3 * DM) + hh * 64;
    size_t obase = (size_t)b * SEQ * DM + hh * 64 + e;

    for (int c0 = p * PLEN; c0 < p * PLEN + PLEN; c0 += 32) {
        #pragma unroll 4
        for (int j = 0; j < 32; j++) {
            const float* r = base + (size_t)(c0 + j) * (3 * DM);
            qs[j][e] = r[e];            // phi(q) precomputed
            ks[j][e] = r[DM + e];       // phi(k) precomputed
            vs[j][e] = r[2 * DM + e];
        }
        __syncthreads();

        float z = zc;
        #pragma unroll
        for (int j = 0; j < 32; j++) { z += ks[j][e]; ps[j][e] = qs[j][e] * z; }
        zc = z;
        __syncthreads();

        if (e < 32) {
            float sum = 0.0f;
            #pragma unroll 8
            for (int d = 0; d < 64; d++) sum += ps[e][d];
            dens[e] = sum + 1e-6f;
        }
        __syncthreads();

        for (int j = 0; j < 32; j++) {
            float ve = vs[j][e];
            float n0 = 0.f, n1 = 0.f, n2 = 0.f, n3 = 0.f;
            #pragma unroll
            for (int d = 0; d < 64; d += 4) {
                S[d + 0] = fmaf(ks[j][d + 0], ve, S[d + 0]); n0 = fmaf(qs[j][d + 0], S[d + 0], n0);
                S[d + 1] = fmaf(ks[j][d + 1], ve, S[d + 1]); n1 = fmaf(qs[j][d + 1], S[d + 1], n1);
                S[d + 2] = fmaf(ks[j][d + 2], ve, S[d + 2]); n2 = fmaf(qs[j][d + 2], S[d + 2], n2);
                S[d + 3] = fmaf(ks[j][d + 3], ve, S[d + 3]); n3 = fmaf(qs[j][d + 3], S[d + 3], n3);
            }
            float o = ((n0 + n1) + (n2 + n3)) / dens[j];
            bf16 hv = __float2bfloat16(o);
            size_t idx = obase + (size_t)(c0 + j) * DM;
            ohi[idx] = hv;
            olo[idx] = __float2bfloat16(o - __bfloat162float(hv));
        }
        __syncthreads();
    }
}

// ================= bf16x3 tensor GEMM (R12 loop; optional phi epilogue) =================
// C = (Ahi+Alo)[M,K] @ (Bhi+Blo)[K,N] + bias (+Res) (relu?) (phi on chunks 0,1?)
#define ASB 72
#define BSB 264
#define AS_E (128 * ASB)
#define BS_E (32 * BSB)
#define TG_SMEM ((AS_E + BS_E) * 2 * 2)

#define MMA_BF16(d, a, b) \
    asm volatile("mma.sync.aligned.m16n8k16.row.col.f32.bf16.bf16.f32 " \
                 "{%0,%1,%2,%3},{%4,%5,%6,%7},{%8,%9},{%0,%1,%2,%3};" \
                 : "+f"((d)[0]), "+f"((d)[1]), "+f"((d)[2]), "+f"((d)[3]) \
                 : "r"((a)[0]), "r"((a)[1]), "r"((a)[2]), "r"((a)[3]), \
                   "r"((b)[0]), "r"((b)[1]))

template <bool RELU, bool RES, bool WF32, bool WBF, bool PHI>
__global__ void __launch_bounds__(256, 2) tgemm_kernel(
    const bf16* __restrict__ Ahi, const bf16* __restrict__ Alo,
    const bf16* __restrict__ Bhi, const bf16* __restrict__ Blo,
    const float* __restrict__ bias, const float* __restrict__ Res,
    float* __restrict__ C, bf16* __restrict__ Chi, bf16* __restrict__ Clo,
    int K, int ldb, int nPerChunk, size_t chunkStride, int ldc, int Nmax)
{
    extern __shared__ __align__(16) unsigned char smem_raw[];
    bf16* As = (bf16*)smem_raw;
    bf16* Bs = As + 2 * AS_E;

    int tid = threadIdx.x;
    int m0 = blockIdx.y * 128;
    int n0 = blockIdx.x * 128;
    int chunk = n0 / nPerChunk;
    size_t boff = (size_t)chunk * chunkStride + (n0 % nPerChunk);
    const bf16* Bbh = Bhi + boff;
    const bf16* Bbl = Blo + boff;

    int arow = tid >> 1, acol = (tid & 1) * 16;
    int brow = tid >> 3, bcol = (tid & 7) * 16;
    const bf16* Agh = Ahi + (size_t)(m0 + arow) * K + acol;
    const bf16* Agl = Alo + (size_t)(m0 + arow) * K + acol;

    int warp = tid >> 5, lane = tid & 31;
    int wm = (warp >> 2) * 64, wn = (warp & 3) * 32;
    int g = lane >> 2, ctg = lane & 3;
    int lrow = lane & 15, lcol8 = (lane >> 4) * 8;

    float acc[4][4][4];
    #pragma unroll
    for (int i = 0; i < 4; i++)
        #pragma unroll
        for (int j = 0; j < 4; j++)
            #pragma unroll
            for (int r = 0; r < 4; r++) acc[i][j][r] = 0.0f;

    int nt = K / 32;

    auto issue = [&](int kt, int buf) {
        bf16* as = As + buf * AS_E;
        bf16* bs = Bs + buf * BS_E;
        {
            unsigned d0 = sptr(as + arow * ASB + acol);
            unsigned d1 = sptr(as + arow * ASB + 32 + acol);
            const bf16* s0 = Agh + kt * 32;
            const bf16* s1 = Agl + kt * 32;
            asm volatile("cp.async.cg.shared.global [%0], [%1], 16;" :: "r"(d0), "l"(s0));
            asm volatile("cp.async.cg.shared.global [%0], [%1], 16;" :: "r"(d0 + 16), "l"(s0 + 8));
            asm volatile("cp.async.cg.shared.global [%0], [%1], 16;" :: "r"(d1), "l"(s1));
            asm volatile("cp.async.cg.shared.global [%0], [%1], 16;" :: "r"(d1 + 16), "l"(s1 + 8));
        }
        {
            unsigned d0 = sptr(bs + brow * BSB + bcol);
            unsigned d1 = sptr(bs + brow * BSB + 128 + bcol);
            const bf16* s0 = Bbh + (size_t)(kt * 32 + brow) * ldb + bcol;
            const bf16* s1 = Bbl + (size_t)(kt * 32 + brow) * ldb + bcol;
            asm volatile("cp.async.cg.shared.global [%0], [%1], 16;" :: "r"(d0), "l"(s0));
            asm volatile("cp.async.cg.shared.global [%0], [%1], 16;" :: "r"(d0 + 16), "l"(s0 + 8));
            asm volatile("cp.async.cg.shared.global [%0], [%1], 16;" :: "r"(d1), "l"(s1));
            asm volatile("cp.async.cg.shared.global [%0], [%1], 16;" :: "r"(d1 + 16), "l"(s1 + 8));
        }
        asm volatile("cp.async.commit_group;");
    };

    issue(0, 0);
    issue(1, 1);

    for (int kt = 0; kt < nt; kt++) {
        if (kt + 1 < nt) asm volatile("cp.async.wait_group 1;");
        else             asm volatile("cp.async.wait_group 0;");
        __syncthreads();

        const bf16* as = As + (kt & 1) * AS_E;
        const bf16* bs = Bs + (kt & 1) * BS_E;

        #pragma unroll
        for (int ks = 0; ks < 32; ks += 16) {
            unsigned bh[4][2], bl[4][2];
            #pragma unroll
            for (int nj = 0; nj < 2; nj++) {
                unsigned addr = sptr(bs + (ks + lrow) * BSB + wn + 16 * nj + lcol8);
                unsigned t0, t1, t2, t3;
                asm volatile("ldmatrix.sync.aligned.m8n8.x4.trans.shared.b16 "
                             "{%0,%1,%2,%3}, [%4];"
                             : "=r"(t0), "=r"(t1), "=r"(t2), "=r"(t3) : "r"(addr));
                bh[2 * nj][0] = t0; bh[2 * nj][1] = t1;
                bh[2 * nj + 1][0] = t2; bh[2 * nj + 1][1] = t3;
                asm volatile("ldmatrix.sync.aligned.m8n8.x4.trans.shared.b16 "
                             "{%0,%1,%2,%3}, [%4];"
                             : "=r"(t0), "=r"(t1), "=r"(t2), "=r"(t3)
                             : "r"(addr + 256));   // lo: +128 elems = +256B
                bl[2 * nj][0] = t0; bl[2 * nj][1] = t1;
                bl[2 * nj + 1][0] = t2; bl[2 * nj + 1][1] = t3;
            }
            #pragma unroll
            for (int i = 0; i < 4; i++) {
                unsigned ah[4], al[4];
                unsigned addr = sptr(as + (wm + 16 * i + lrow) * ASB + ks + lcol8);
                asm volatile("ldmatrix.sync.aligned.m8n8.x4.shared.b16 "
                             "{%0,%1,%2,%3}, [%4];"
                             : "=r"(ah[0]), "=r"(ah[1]), "=r"(ah[2]), "=r"(ah[3])
                             : "r"(addr));
                asm volatile("ldmatrix.sync.aligned.m8n8.x4.shared.b16 "
                             "{%0,%1,%2,%3}, [%4];"
                             : "=r"(al[0]), "=r"(al[1]), "=r"(al[2]), "=r"(al[3])
                             : "r"(addr + 64));    // lo: +32 elems = +64B
                #pragma unroll
                for (int j = 0; j < 4; j++) {
                    MMA_BF16(acc[i][j], ah, bh[j]);
                    MMA_BF16(acc[i][j], ah, bl[j]);
                    MMA_BF16(acc[i][j], al, bh[j]);
                }
            }
        }
        __syncthreads();
        if (kt + 2 < nt) issue(kt + 2, kt & 1);
    }

    // ---- epilogue ----
    bool phi = PHI && (chunk < 2);   // q,k chunks get elu+1; v untouched
    #pragma unroll
    for (int i = 0; i < 4; i++) {
        int mrow = m0 + wm + 16 * i + g;
        #pragma unroll
        for (int j = 0; j < 4; j++) {
            int n = n0 + wn + 8 * j + 2 * ctg;
            if (n >= Nmax) continue;
            float2 bv = *(const float2*)(bias + n);
            float v0 = acc[i][j][0] + bv.x, v1 = acc[i][j][1] + bv.y;
            float v2 = acc[i][j][2] + bv.x, v3 = acc[i][j][3] + bv.y;
            if (RES) {
                float2 r0 = *(const float2*)(Res + (size_t)mrow * ldc + n);
                float2 r1 = *(const float2*)(Res + (size_t)(mrow + 8) * ldc + n);
                v0 += r0.x; v1 += r0.y; v2 += r1.x; v3 += r1.y;
            }
            if (RELU) {
                v0 = fmaxf(v0, 0.0f); v1 = fmaxf(v1, 0.0f);
                v2 = fmaxf(v2, 0.0f); v3 = fmaxf(v3, 0.0f);
            }
            if (PHI && phi) {
                v0 = (v0 > 0.0f) ? v0 + 1.0f : expf(v0);
                v1 = (v1 > 0.0f) ? v1 + 1.0f : expf(v1);
                v2 = (v2 > 0.0f) ? v2 + 1.0f : expf(v2);
                v3 = (v3 > 0.0f) ? v3 + 1.0f : expf(v3);
            }
            if (WF32) {
                *(float2*)(C + (size_t)mrow * ldc + n) = make_float2(v0, v1);
                *(float2*)(C + (size_t)(mrow + 8) * ldc + n) = make_float2(v2, v3);
            }
            if (WBF) {
                unsigned hp, lp;
                split2(v0, v1, hp, lp);
                *(unsigned*)(Chi + (size_t)mrow * ldc + n) = hp;
                *(unsigned*)(Clo + (size_t)mrow * ldc + n) = lp;
                split2(v2, v3, hp, lp);
                *(unsigned*)(Chi + (size_t)(mrow + 8) * ldc + n) = hp;
                *(unsigned*)(Clo + (size_t)(mrow + 8) * ldc + n) = lp;
            }
        }
    }
}

// ---------------- launch ----------------
extern "C" void kernel_launch(void* const* d_in, const int* in_sizes, int n_in,
                              void* d_out, int out_size)
{
    const int*   x    = (const int*)d_in[0];
    const float* emb  = (const float*)d_in[1];
    const float* Wqkv = (const float*)d_in[2];
    const float* bqkv = (const float*)d_in[3];
    const float* Wo   = (const float*)d_in[4];
    const float* bo   = (const float*)d_in[5];
    const float* ln1g = (const float*)d_in[6];
    const float* ln1b = (const float*)d_in[7];
    const float* W1   = (const float*)d_in[8];
    const float* b1   = (const float*)d_in[9];
    const float* W2   = (const float*)d_in[10];
    const float* b2   = (const float*)d_in[11];
    const float* ln2g = (const float*)d_in[12];
    const float* ln2b = (const float*)d_in[13];
    const float* lnfg = (const float*)d_in[14];
    const float* lnfb = (const float*)d_in[15];
    const float* Wout = (const float*)d_in[16];
    const float* bout = (const float*)d_in[17];
    float* out = (float*)d_out;

    float *h, *qkv, *state, *zbuf, *boutp;
    bf16 *hhi, *hlo, *ahi, *alo, *fhi, *flo, *whi, *wlo, *wohi, *wolo;
    cudaGetSymbolAddress((void**)&h,     g_h);
    cudaGetSymbolAddress((void**)&qkv,   g_qkv);
    cudaGetSymbolAddress((void**)&state, g_state);
    cudaGetSymbolAddress((void**)&zbuf,  g_z);
    cudaGetSymbolAddress((void**)&hhi,   g_h_hi);
    cudaGetSymbolAddress((void**)&hlo,   g_h_lo);
    cudaGetSymbolAddress((void**)&ahi,   g_attn_hi);
    cudaGetSymbolAddress((void**)&alo,   g_attn_lo);
    cudaGetSymbolAddress((void**)&fhi,   g_ff_hi);
    cudaGetSymbolAddress((void**)&flo,   g_ff_lo);
    cudaGetSymbolAddress((void**)&whi,   g_w_hi);
    cudaGetSymbolAddress((void**)&wlo,   g_w_lo);
    cudaGetSymbolAddress((void**)&wohi,  g_wout_hi);
    cudaGetSymbolAddress((void**)&wolo,  g_wout_lo);
    cudaGetSymbolAddress((void**)&boutp, g_bout);

    cudaFuncSetAttribute(tgemm_kernel<false, false, true, false, true>,
                         cudaFuncAttributeMaxDynamicSharedMemorySize, TG_SMEM);
    cudaFuncSetAttribute(tgemm_kernel<false, false, true, false, false>,
                         cudaFuncAttributeMaxDynamicSharedMemorySize, TG_SMEM);
    cudaFuncSetAttribute(tgemm_kernel<false, true, true, false, false>,
                         cudaFuncAttributeMaxDynamicSharedMemorySize, TG_SMEM);
    cudaFuncSetAttribute(tgemm_kernel<true, false, false, true, false>,
                         cudaFuncAttributeMaxDynamicSharedMemorySize, TG_SMEM);

    // weight prep
    split_kernel<<<(OFF_WO) / 4 / 256, 256>>>(Wqkv, whi + OFF_QKV, wlo + OFF_QKV, OFF_WO / 4);
    split_kernel<<<(OFF_W1 - OFF_WO) / 4 / 256, 256>>>(Wo, whi + OFF_WO, wlo + OFF_WO, (OFF_W1 - OFF_WO) / 4);
    split_kernel<<<(OFF_W2 - OFF_W1) / 4 / 256, 256>>>(W1, whi + OFF_W1, wlo + OFF_W1, (OFF_W2 - OFF_W1) / 4);
    split_kernel<<<(W_TOTAL - OFF_W2) / 4 / 256, 256>>>(W2, whi + OFF_W2, wlo + OFF_W2, (W_TOTAL - OFF_W2) / 4);
    wout_split_kernel<<<DM, 128>>>(Wout, wohi, wolo);
    bpad_kernel<<<1, DM>>>(bout, boutp);

    embed_kernel<<<TOKENS, 128>>>(x, emb, h, hhi, hlo);

    dim3 gQKV(12, TOKENS / 128);
    dim3 gN512(4, TOKENS / 128);
    dim3 gN2048(16, TOKENS / 128);
    dim3 gAttn(32, NP);

    for (int l = 0; l < NLAYER; l++) {
        // qkv = h @ [Wq|Wk|Wv] + b, with phi applied to q,k chunks in epilogue
        tgemm_kernel<false, false, true, false, true><<<gQKV, 256, TG_SMEM>>>(
            hhi, hlo,
            whi + OFF_QKV + (size_t)l * 3 * DM * DM, wlo + OFF_QKV + (size_t)l * 3 * DM * DM,
            bqkv + (size_t)l * 3 * DM, nullptr,
            qkv, nullptr, nullptr,
            DM, DM, DM, (size_t)DM * DM, 3 * DM, 3 * DM);

        attn_sums_kernel<<<gAttn, 64>>>(qkv, state, zbuf);
        attn_prefix_kernel<<<32, 256>>>(state, zbuf);
        attn_scan_kernel<<<gAttn, 64>>>(qkv, state, zbuf, ahi, alo);

        // h = h + attn @ Wo + bo
        tgemm_kernel<false, true, true, false, false><<<gN512, 256, TG_SMEM>>>(
            ahi, alo,
            whi + OFF_WO + (size_t)l * DM * DM, wlo + OFF_WO + (size_t)l * DM * DM,
            bo + (size_t)l * DM, h,
            h, nullptr, nullptr,
            DM, DM, DM, 0, DM, DM);
        ln_kernel<<<TOKENS, 128>>>(h, ln1g + l * DM, ln1b + l * DM, h, hhi, hlo);

        // ff = relu(h @ W1 + b1)  (bf16 hi/lo out)
        tgemm_kernel<true, false, false, true, false><<<gN2048, 256, TG_SMEM>>>(
            hhi, hlo,
            whi + OFF_W1 + (size_t)l * DM * DFF, wlo + OFF_W1 + (size_t)l * DM * DFF,
            b1 + (size_t)l * DFF, nullptr,
            nullptr, fhi, flo,
            DM, DFF, DFF, 0, DFF, DFF);

        // h = h + ff @ W2 + b2
        tgemm_kernel<false, true, true, false, false><<<gN512, 256, TG_SMEM>>>(
            fhi, flo,
            whi + OFF_W2 + (size_t)l * DFF * DM, wlo + OFF_W2 + (size_t)l * DFF * DM,
            b2 + (size_t)l * DM, h,
            h, nullptr, nullptr,
            DFF, DM, DM, 0, DM, DM);
        ln_kernel<<<TOKENS, 128>>>(h, ln2g + l * DM, ln2b + l * DM, h, hhi, hlo);
    }

    ln_kernel<<<TOKENS, 128>>>(h, lnfg, lnfb, h, hhi, hlo);
    // out = h @ Wout + bout  (tensor path, padded N=512, guarded to 400)
    tgemm_kernel<false, false, true, false, false><<<gN512, 256, TG_SMEM>>>(
        hhi, hlo, wohi, wolo, boutp, nullptr,
        out, nullptr, nullptr,
        DM, DM, DM, 0, NVOCAB, NVOCAB);
}